// round 1
// baseline (speedup 1.0000x reference)
#include <cuda_runtime.h>
#include <math.h>

// Problem constants: B=8, N=8192, C=256, K=8, nblocks=8, blk=32
#define TOK_TOTAL 65536          // B*N
#define N_TOK     8192
#define C_DIM     256
#define K_NB      8
#define EPS_W     0.05f
#define OME_W     0.95f

// Scratch (allocation-free rule: __device__ globals)
__device__ float g_t[(size_t)TOK_TOTAL * C_DIM];   // 64 MB monarch output
__device__ float g_w[(size_t)TOK_TOTAL * K_NB];    // eps-scaled softmax weights

// ---------------------------------------------------------------------------
// Kernel 0: per-token softmax(-distance) * eps, stored once, reused by k1/k2.
// ---------------------------------------------------------------------------
__global__ void softmax_k(const float* __restrict__ dist) {
    int tok = blockIdx.x * blockDim.x + threadIdx.x;
    if (tok >= TOK_TOTAL) return;
    const float4* dp = (const float4*)(dist + (size_t)tok * K_NB);
    float4 a = dp[0], b4 = dp[1];
    float d[8] = {a.x, a.y, a.z, a.w, b4.x, b4.y, b4.z, b4.w};
    float m = d[0];
#pragma unroll
    for (int k = 1; k < 8; k++) m = fminf(m, d[k]);
    float e[8];
    float s = 0.f;
#pragma unroll
    for (int k = 0; k < 8; k++) { e[k] = expf(m - d[k]); s += e[k]; }
    float inv = EPS_W / s;
    float4* wp = (float4*)(g_w + (size_t)tok * K_NB);
    wp[0] = make_float4(e[0]*inv, e[1]*inv, e[2]*inv, e[3]*inv);
    wp[1] = make_float4(e[4]*inv, e[5]*inv, e[6]*inv, e[7]*inv);
}

// ---------------------------------------------------------------------------
// Kernel 1: fused rectify1 + monarch. 256 threads, 4 tokens per round,
// 8 rounds per block (32 tokens/block, 2048 blocks).
//   Phase A0: stage weights/idx to smem
//   Phase A : float4 gather of self + 8 neighbors -> sv[t][256]
//   Phase B : stage1 butterfly, o1[k*32+q]; written TRANSPOSED (f=r*8+l ->
//             so1[l*36+r], pad 36 => conflict-free STS and LDS.128 reads)
//   Phase C : stage2 butterfly + bias, write t to scratch
// ---------------------------------------------------------------------------
__global__ void __launch_bounds__(256, 2) k1_rect_monarch(
        const float* __restrict__ x,
        const int*   __restrict__ idx,
        const float* __restrict__ w1,
        const float* __restrict__ w2,
        const float* __restrict__ bias) {
    __shared__ __align__(16) float sv[4][C_DIM];
    __shared__ __align__(16) float so1[4][288];     // 8 * 36 padded
    __shared__ float sw[32];
    __shared__ int   si[32];

    const int tid = threadIdx.x;

    // Per-thread monarch weight rows (register resident)
    float w1r[32], w2r[32];
    {
        const float4* p1 = (const float4*)(w1 + (size_t)tid * 32);
#pragma unroll
        for (int i = 0; i < 8; i++) {
            float4 f = p1[i];
            w1r[4*i+0] = f.x; w1r[4*i+1] = f.y; w1r[4*i+2] = f.z; w1r[4*i+3] = f.w;
        }
        const float4* p2 = (const float4*)(w2 + (size_t)(tid & 7) * 1024 + (size_t)(tid >> 3) * 32);
#pragma unroll
        for (int i = 0; i < 8; i++) {
            float4 f = p2[i];
            w2r[4*i+0] = f.x; w2r[4*i+1] = f.y; w2r[4*i+2] = f.z; w2r[4*i+3] = f.w;
        }
    }
    const float br = bias[tid];

    const int t = tid >> 6;          // token-in-round 0..3
    const int q = tid & 63;          // float4 quad 0..63
    const int tokBlock = blockIdx.x * 32;            // 32 tokens per block
    const int b = tokBlock >> 13;                    // batch (N=8192)
    const float* xb = x + ((size_t)b << 13) * C_DIM; // batch base for gathers

    const int kbase = tid & 0xE0;                    // stage1 input block base
    const int widx  = (tid & 7) * 36 + (tid >> 3);   // transposed o1 slot
    const int lbase = (tid & 7) * 36;                // stage2 input row base

#pragma unroll 1
    for (int r = 0; r < 8; r++) {
        const int tok0 = tokBlock + r * 4;

        // ---- Phase A0: stage per-token weights and neighbor indices
        if (tid < 32)       sw[tid]      = g_w[(size_t)tok0 * 8 + tid];
        else if (tid < 64)  si[tid - 32] = idx[(size_t)tok0 * 8 + (tid - 32)];
        __syncthreads();

        // ---- Phase A: distance-weighted gather (float4 vectorized)
        {
            const int tok = tok0 + t;
            float4 a = ((const float4*)(x + (size_t)tok * C_DIM))[q];
            float4 acc = make_float4(OME_W*a.x, OME_W*a.y, OME_W*a.z, OME_W*a.w);
#pragma unroll
            for (int k = 0; k < 8; k++) {
                float wk = sw[t*8 + k];
                int   nb = si[t*8 + k];
                float4 v = ((const float4*)(xb + (size_t)nb * C_DIM))[q];
                acc.x = fmaf(wk, v.x, acc.x);
                acc.y = fmaf(wk, v.y, acc.y);
                acc.z = fmaf(wk, v.z, acc.z);
                acc.w = fmaf(wk, v.w, acc.w);
            }
            ((float4*)sv[t])[q] = acc;
        }
        __syncthreads();

        // ---- Phase B: stage1 (o1[k*32+q] = sum_p w1[k,q,p] * v[k*32+p])
#pragma unroll
        for (int tt = 0; tt < 4; tt++) {
            const float4* vp = (const float4*)(&sv[tt][kbase]);
            float o = 0.f;
#pragma unroll
            for (int p = 0; p < 8; p++) {
                float4 f = vp[p];
                o = fmaf(w1r[4*p+0], f.x, o);
                o = fmaf(w1r[4*p+1], f.y, o);
                o = fmaf(w1r[4*p+2], f.z, o);
                o = fmaf(w1r[4*p+3], f.w, o);
            }
            so1[tt][widx] = o;   // transposed: flat f=tid -> (l=f&7, r=f>>3)
        }
        __syncthreads();

        // ---- Phase C: stage2 (out[s*8+l] = sum_r w2[l,s,r] * o1[r*8+l] + bias)
#pragma unroll
        for (int tt = 0; tt < 4; tt++) {
            const float4* op = (const float4*)(&so1[tt][lbase]);
            float acc = br;
#pragma unroll
            for (int p = 0; p < 8; p++) {
                float4 f = op[p];
                acc = fmaf(w2r[4*p+0], f.x, acc);
                acc = fmaf(w2r[4*p+1], f.y, acc);
                acc = fmaf(w2r[4*p+2], f.z, acc);
                acc = fmaf(w2r[4*p+3], f.w, acc);
            }
            g_t[(size_t)(tok0 + tt) * C_DIM + tid] = acc;
        }
        __syncthreads();
    }
}

// ---------------------------------------------------------------------------
// Kernel 2: rectify2 on t + rf. Pure float4 gather/axpy (L2-bound).
// 256 threads, 4 tokens per round, 8 rounds/block (2048 blocks).
// ---------------------------------------------------------------------------
__global__ void __launch_bounds__(256, 4) k2_rect_add(
        const float* __restrict__ rf,
        const int*   __restrict__ idx,
        float*       __restrict__ out) {
    __shared__ float sw[32];
    __shared__ int   si[32];

    const int tid = threadIdx.x;
    const int t = tid >> 6;
    const int q = tid & 63;
    const int tokBlock = blockIdx.x * 32;
    const int b = tokBlock >> 13;
    const float* tb = g_t + ((size_t)b << 13) * C_DIM;

#pragma unroll 1
    for (int r = 0; r < 8; r++) {
        const int tok0 = tokBlock + r * 4;
        __syncthreads();   // WAR guard on sw/si across rounds
        if (tid < 32)       sw[tid]      = g_w[(size_t)tok0 * 8 + tid];
        else if (tid < 64)  si[tid - 32] = idx[(size_t)tok0 * 8 + (tid - 32)];
        __syncthreads();

        const int tok = tok0 + t;
        float4 s = ((const float4*)(g_t + (size_t)tok * C_DIM))[q];
        float4 acc = make_float4(OME_W*s.x, OME_W*s.y, OME_W*s.z, OME_W*s.w);
#pragma unroll
        for (int k = 0; k < 8; k++) {
            float wk = sw[t*8 + k];
            int   nb = si[t*8 + k];
            float4 v = ((const float4*)(tb + (size_t)nb * C_DIM))[q];
            acc.x = fmaf(wk, v.x, acc.x);
            acc.y = fmaf(wk, v.y, acc.y);
            acc.z = fmaf(wk, v.z, acc.z);
            acc.w = fmaf(wk, v.w, acc.w);
        }
        float4 rv = ((const float4*)(rf + (size_t)tok * C_DIM))[q];
        acc.x += rv.x; acc.y += rv.y; acc.z += rv.z; acc.w += rv.w;
        ((float4*)(out + (size_t)tok * C_DIM))[q] = acc;
    }
}

// ---------------------------------------------------------------------------
extern "C" void kernel_launch(void* const* d_in, const int* in_sizes, int n_in,
                              void* d_out, int out_size) {
    const float* x    = (const float*)d_in[0];
    const float* dist = (const float*)d_in[1];
    const int*   idx  = (const int*)  d_in[2];
    const float* rf   = (const float*)d_in[3];
    const float* w1   = (const float*)d_in[4];
    const float* w2   = (const float*)d_in[5];
    const float* bias = (const float*)d_in[6];
    float* out = (float*)d_out;

    softmax_k<<<TOK_TOTAL / 256, 256>>>(dist);
    k1_rect_monarch<<<TOK_TOTAL / 32, 256>>>(x, idx, w1, w2, bias);
    k2_rect_add<<<TOK_TOTAL / 32, 256>>>(rf, idx, out);
}

// round 2
// speedup vs baseline: 1.0991x; 1.0991x over previous
#include <cuda_runtime.h>
#include <math.h>

// Problem constants: B=8, N=8192, C=256, K=8, nblocks=8, blk=32
#define TOK_TOTAL 65536          // B*N
#define N_TOK     8192
#define C_DIM     256
#define K_NB      8
#define EPS_W     0.05f
#define OME_W     0.95f

// Scratch (allocation-free rule: __device__ globals)
__device__ float g_t[(size_t)TOK_TOTAL * C_DIM];   // 64 MB monarch output
__device__ float g_w[(size_t)TOK_TOTAL * K_NB];    // eps-scaled softmax weights

// ---------------------------------------------------------------------------
// Kernel 0: per-token eps*softmax(-distance). d in [0,1) -> exp(-d) in [.37,1]
// so no max-subtraction needed; __expf (MUFU) is plenty accurate.
// ---------------------------------------------------------------------------
__global__ void softmax_k(const float* __restrict__ dist) {
    int tok = blockIdx.x * blockDim.x + threadIdx.x;
    if (tok >= TOK_TOTAL) return;
    const float4* dp = (const float4*)(dist + (size_t)tok * K_NB);
    float4 a = dp[0], b4 = dp[1];
    float d[8] = {a.x, a.y, a.z, a.w, b4.x, b4.y, b4.z, b4.w};
    float e[8];
    float s = 0.f;
#pragma unroll
    for (int k = 0; k < 8; k++) { e[k] = __expf(-d[k]); s += e[k]; }
    float inv = EPS_W / s;
    float4* wp = (float4*)(g_w + (size_t)tok * K_NB);
    wp[0] = make_float4(e[0]*inv, e[1]*inv, e[2]*inv, e[3]*inv);
    wp[1] = make_float4(e[4]*inv, e[5]*inv, e[6]*inv, e[7]*inv);
}

// ---------------------------------------------------------------------------
// Kernel 1: fused rectify1 + monarch, SOFTWARE PIPELINED.
// 256 threads, 4 tokens per round, 8 rounds per block (32 tokens, 2048 blocks).
// Round r's 9 gather rows (self + 8 neighbors) are LDG'd into registers during
// round r-1's monarch phases (B+C), so L2 gather latency hides behind compute.
// sv is double-buffered so only 2 barriers/round are needed.
// ---------------------------------------------------------------------------
__global__ void __launch_bounds__(256, 2) k1_rect_monarch(
        const float* __restrict__ x,
        const int*   __restrict__ idx,
        const float* __restrict__ w1,
        const float* __restrict__ w2,
        const float* __restrict__ bias) {
    __shared__ __align__(16) float sv[2][4][C_DIM];
    __shared__ __align__(16) float so1[4][288];     // 8 * 36 padded

    const int tid = threadIdx.x;

    // Per-thread monarch weight rows (register resident)
    float w1r[32], w2r[32];
    {
        const float4* p1 = (const float4*)(w1 + (size_t)tid * 32);
#pragma unroll
        for (int i = 0; i < 8; i++) {
            float4 f = p1[i];
            w1r[4*i+0] = f.x; w1r[4*i+1] = f.y; w1r[4*i+2] = f.z; w1r[4*i+3] = f.w;
        }
        const float4* p2 = (const float4*)(w2 + (size_t)(tid & 7) * 1024 + (size_t)(tid >> 3) * 32);
#pragma unroll
        for (int i = 0; i < 8; i++) {
            float4 f = p2[i];
            w2r[4*i+0] = f.x; w2r[4*i+1] = f.y; w2r[4*i+2] = f.z; w2r[4*i+3] = f.w;
        }
    }
    const float br = bias[tid];

    const int t = tid >> 6;          // token-in-round 0..3
    const int q = tid & 63;          // float4 quad 0..63
    const int tokBlock = blockIdx.x * 32;            // 32 tokens per block
    const int b = tokBlock >> 13;                    // batch (N=8192)
    const float* xb = x + ((size_t)b << 13) * C_DIM; // batch base for gathers

    const int kbase = tid & 0xE0;                    // stage1 input block base
    const int widx  = (tid & 7) * 36 + (tid >> 3);   // transposed o1 slot
    const int lbase = (tid & 7) * 36;                // stage2 input row base

    // ---- Prefetch round 0: per-token weights, idx, gather rows -> registers
    float4 v[9];
    float  swr[8];
    int    offs[8];
    {
        const int tok = tokBlock + t;
        const float4* wp = (const float4*)(g_w + (size_t)tok * 8);
        float4 wa = wp[0], wb = wp[1];
        swr[0]=wa.x; swr[1]=wa.y; swr[2]=wa.z; swr[3]=wa.w;
        swr[4]=wb.x; swr[5]=wb.y; swr[6]=wb.z; swr[7]=wb.w;
        const int4* ip = (const int4*)(idx + (size_t)tok * 8);
        int4 ia = ip[0], ib = ip[1];
        offs[0]=ia.x*C_DIM; offs[1]=ia.y*C_DIM; offs[2]=ia.z*C_DIM; offs[3]=ia.w*C_DIM;
        offs[4]=ib.x*C_DIM; offs[5]=ib.y*C_DIM; offs[6]=ib.z*C_DIM; offs[7]=ib.w*C_DIM;
        v[0] = ((const float4*)(x + (size_t)tok * C_DIM))[q];
#pragma unroll
        for (int k = 0; k < 8; k++)
            v[k+1] = ((const float4*)(xb + offs[k]))[q];
    }

#pragma unroll 1
    for (int r = 0; r < 8; r++) {
        const int buf  = r & 1;
        const int tok0 = tokBlock + r * 4;

        // ---- Consume prefetched gather into the weighted sum; stage to smem
        {
            float4 acc = make_float4(OME_W*v[0].x, OME_W*v[0].y, OME_W*v[0].z, OME_W*v[0].w);
#pragma unroll
            for (int k = 0; k < 8; k++) {
                float wk = swr[k];
                acc.x = fmaf(wk, v[k+1].x, acc.x);
                acc.y = fmaf(wk, v[k+1].y, acc.y);
                acc.z = fmaf(wk, v[k+1].z, acc.z);
                acc.w = fmaf(wk, v[k+1].w, acc.w);
            }
            ((float4*)sv[buf][t])[q] = acc;
        }

        // ---- Issue next round's prefetch (overlaps with phases B+C below)
        if (r < 7) {
            const int tok = tok0 + 4 + t;
            const float4* wp = (const float4*)(g_w + (size_t)tok * 8);
            float4 wa = wp[0], wb = wp[1];
            swr[0]=wa.x; swr[1]=wa.y; swr[2]=wa.z; swr[3]=wa.w;
            swr[4]=wb.x; swr[5]=wb.y; swr[6]=wb.z; swr[7]=wb.w;
            const int4* ip = (const int4*)(idx + (size_t)tok * 8);
            int4 ia = ip[0], ib = ip[1];
            offs[0]=ia.x*C_DIM; offs[1]=ia.y*C_DIM; offs[2]=ia.z*C_DIM; offs[3]=ia.w*C_DIM;
            offs[4]=ib.x*C_DIM; offs[5]=ib.y*C_DIM; offs[6]=ib.z*C_DIM; offs[7]=ib.w*C_DIM;
            v[0] = ((const float4*)(x + (size_t)tok * C_DIM))[q];
#pragma unroll
            for (int k = 0; k < 8; k++)
                v[k+1] = ((const float4*)(xb + offs[k]))[q];
        }

        __syncthreads();   // sv[buf] visible; C(r-1) done reading so1

        // ---- Phase B: stage1 (o1[k*32+q] = sum_p w1[k,q,p] * v[k*32+p])
#pragma unroll
        for (int tt = 0; tt < 4; tt++) {
            const float4* vp = (const float4*)(&sv[buf][tt][kbase]);
            float o = 0.f;
#pragma unroll
            for (int p = 0; p < 8; p++) {
                float4 f = vp[p];
                o = fmaf(w1r[4*p+0], f.x, o);
                o = fmaf(w1r[4*p+1], f.y, o);
                o = fmaf(w1r[4*p+2], f.z, o);
                o = fmaf(w1r[4*p+3], f.w, o);
            }
            so1[tt][widx] = o;   // transposed: flat f=tid -> (l=f&7, r=f>>3)
        }
        __syncthreads();

        // ---- Phase C: stage2 (out[s*8+l] = sum_r w2[l,s,r] * o1[r*8+l] + bias)
#pragma unroll
        for (int tt = 0; tt < 4; tt++) {
            const float4* op = (const float4*)(&so1[tt][lbase]);
            float acc = br;
#pragma unroll
            for (int p = 0; p < 8; p++) {
                float4 f = op[p];
                acc = fmaf(w2r[4*p+0], f.x, acc);
                acc = fmaf(w2r[4*p+1], f.y, acc);
                acc = fmaf(w2r[4*p+2], f.z, acc);
                acc = fmaf(w2r[4*p+3], f.w, acc);
            }
            g_t[(size_t)(tok0 + tt) * C_DIM + tid] = acc;
        }
        // no trailing barrier: next round's sv store targets the other buffer,
        // and barrier1 of the next round protects so1 against its next writer.
    }
}

// ---------------------------------------------------------------------------
// Kernel 2: rectify2 on t + rf. WARP-PER-TOKEN, barrier-free.
// Lane handles float4 quads {lane, lane+32}; weights/idx broadcast via shfl.
// ~20 independent LDG.128 in flight per warp -> L2-bandwidth bound.
// ---------------------------------------------------------------------------
__global__ void __launch_bounds__(256) k2_rect_add(
        const float* __restrict__ rf,
        const int*   __restrict__ idx,
        float*       __restrict__ out) {
    const int lane = threadIdx.x & 31;
    const int warp = threadIdx.x >> 5;
    const int tok  = blockIdx.x * 8 + warp;     // grid = TOK_TOTAL/8
    const int b    = tok >> 13;
    const float* tb = g_t + ((size_t)b << 13) * C_DIM;

    // lanes 0-7 fetch this token's weights and neighbor indices
    float wv = 0.f; int iv = 0;
    if (lane < 8) {
        wv = g_w[(size_t)tok * 8 + lane];
        iv = idx[(size_t)tok * 8 + lane];
    }

    const float4* trow = (const float4*)(g_t + (size_t)tok * C_DIM);
    float4 s0 = trow[lane], s1 = trow[lane + 32];
    const float4* rrow = (const float4*)(rf + (size_t)tok * C_DIM);
    float4 r0 = rrow[lane], r1 = rrow[lane + 32];

    float4 a0 = make_float4(OME_W*s0.x + r0.x, OME_W*s0.y + r0.y,
                            OME_W*s0.z + r0.z, OME_W*s0.w + r0.w);
    float4 a1 = make_float4(OME_W*s1.x + r1.x, OME_W*s1.y + r1.y,
                            OME_W*s1.z + r1.z, OME_W*s1.w + r1.w);

#pragma unroll
    for (int k = 0; k < 8; k++) {
        float wk = __shfl_sync(0xFFFFFFFFu, wv, k);
        int   nb = __shfl_sync(0xFFFFFFFFu, iv, k);
        const float4* nr = (const float4*)(tb + (size_t)nb * C_DIM);
        float4 n0 = nr[lane], n1 = nr[lane + 32];
        a0.x = fmaf(wk, n0.x, a0.x);  a0.y = fmaf(wk, n0.y, a0.y);
        a0.z = fmaf(wk, n0.z, a0.z);  a0.w = fmaf(wk, n0.w, a0.w);
        a1.x = fmaf(wk, n1.x, a1.x);  a1.y = fmaf(wk, n1.y, a1.y);
        a1.z = fmaf(wk, n1.z, a1.z);  a1.w = fmaf(wk, n1.w, a1.w);
    }

    float4* orow = (float4*)(out + (size_t)tok * C_DIM);
    orow[lane]      = a0;
    orow[lane + 32] = a1;
}

// ---------------------------------------------------------------------------
extern "C" void kernel_launch(void* const* d_in, const int* in_sizes, int n_in,
                              void* d_out, int out_size) {
    const float* x    = (const float*)d_in[0];
    const float* dist = (const float*)d_in[1];
    const int*   idx  = (const int*)  d_in[2];
    const float* rf   = (const float*)d_in[3];
    const float* w1   = (const float*)d_in[4];
    const float* w2   = (const float*)d_in[5];
    const float* bias = (const float*)d_in[6];
    float* out = (float*)d_out;

    softmax_k<<<TOK_TOTAL / 256, 256>>>(dist);
    k1_rect_monarch<<<TOK_TOTAL / 32, 256>>>(x, idx, w1, w2, bias);
    k2_rect_add<<<TOK_TOTAL / 8, 256>>>(rf, idx, out);
}